// round 1
// baseline (speedup 1.0000x reference)
#include <cuda_runtime.h>
#include <math.h>

#define B_  32
#define C_  256
#define H_  128
#define W_  128
#define HW  (H_ * W_)
#define HW4 (HW / 4)

// Scratch: avg/max per pixel, and gate. 2 MB each.
__device__ float g_avg[B_ * HW];
__device__ float g_max[B_ * HW];
__device__ float g_gate[B_ * HW];

// ---------------------------------------------------------------------------
// K1: channel-wise mean & max over y.  One thread = 4 consecutive pixels.
// ---------------------------------------------------------------------------
__global__ void __launch_bounds__(256) reduce_kernel(const float* __restrict__ y) {
    int idx = blockIdx.x * blockDim.x + threadIdx.x;     // over B*HW4
    if (idx >= B_ * HW4) return;
    int b  = idx / HW4;
    int p4 = idx - b * HW4;

    const float4* base = reinterpret_cast<const float4*>(y) + (size_t)b * C_ * HW4 + p4;

    float4 s = make_float4(0.f, 0.f, 0.f, 0.f);
    float4 m = make_float4(-INFINITY, -INFINITY, -INFINITY, -INFINITY);

    #pragma unroll 4
    for (int c = 0; c < C_; c++) {
        float4 v = __ldcs(base + (size_t)c * HW4);
        s.x += v.x; s.y += v.y; s.z += v.z; s.w += v.w;
        m.x = fmaxf(m.x, v.x); m.y = fmaxf(m.y, v.y);
        m.z = fmaxf(m.z, v.z); m.w = fmaxf(m.w, v.w);
    }
    const float inv = 1.0f / (float)C_;
    s.x *= inv; s.y *= inv; s.z *= inv; s.w *= inv;

    reinterpret_cast<float4*>(g_avg)[idx] = s;
    reinterpret_cast<float4*>(g_max)[idx] = m;
}

// ---------------------------------------------------------------------------
// K2: 3x3 conv over [avg, max] channels + sigmoid -> gate.  One thread/pixel.
// ---------------------------------------------------------------------------
__global__ void __launch_bounds__(256) gate_kernel(const float* __restrict__ conv_w) {
    int idx = blockIdx.x * blockDim.x + threadIdx.x;     // over B*HW
    if (idx >= B_ * HW) return;
    int b  = idx / HW;
    int hw = idx - b * HW;
    int h  = hw / W_;
    int w  = hw - h * W_;

    // conv_w layout: [1, 2, 3, 3] -> w[0..8] for avg channel, w[9..17] for max
    float acc = 0.f;
    #pragma unroll
    for (int kh = -1; kh <= 1; kh++) {
        int hh = h + kh;
        if (hh < 0 || hh >= H_) continue;
        #pragma unroll
        for (int kw = -1; kw <= 1; kw++) {
            int ww = w + kw;
            if (ww < 0 || ww >= W_) continue;
            int si = b * HW + hh * W_ + ww;
            int ki = (kh + 1) * 3 + (kw + 1);
            acc = fmaf(g_avg[si], conv_w[ki],       acc);
            acc = fmaf(g_max[si], conv_w[9 + ki],   acc);
        }
    }
    g_gate[idx] = 1.0f / (1.0f + expf(-acc));
}

// ---------------------------------------------------------------------------
// K3: out = x * gate (broadcast over channels).  float4 streaming.
// ---------------------------------------------------------------------------
__global__ void __launch_bounds__(256) mul_kernel(const float* __restrict__ x,
                                                  float* __restrict__ out) {
    long long idx = (long long)blockIdx.x * blockDim.x + threadIdx.x;  // over B*C*HW4
    const long long total4 = (long long)B_ * C_ * HW4;
    if (idx >= total4) return;

    int p4 = (int)(idx % HW4);
    int b  = (int)(idx / ((long long)C_ * HW4));

    float4 g  = reinterpret_cast<const float4*>(g_gate)[b * HW4 + p4];  // L2-resident
    float4 xv = __ldcs(reinterpret_cast<const float4*>(x) + idx);
    float4 o;
    o.x = xv.x * g.x; o.y = xv.y * g.y; o.z = xv.z * g.z; o.w = xv.w * g.w;
    __stcs(reinterpret_cast<float4*>(out) + idx, o);
}

// ---------------------------------------------------------------------------
extern "C" void kernel_launch(void* const* d_in, const int* in_sizes, int n_in,
                              void* d_out, int out_size) {
    const float* x      = (const float*)d_in[0];
    const float* y      = (const float*)d_in[1];
    const float* conv_w = (const float*)d_in[2];
    float* out          = (float*)d_out;

    {
        int n = B_ * HW4;               // 131072 threads
        reduce_kernel<<<(n + 255) / 256, 256>>>(y);
    }
    {
        int n = B_ * HW;                // 524288 threads
        gate_kernel<<<(n + 255) / 256, 256>>>(conv_w);
    }
    {
        long long n = (long long)B_ * C_ * HW4;   // 33554432 threads
        mul_kernel<<<(int)((n + 255) / 256), 256>>>(x, out);
    }
}